// round 15
// baseline (speedup 1.0000x reference)
#include <cuda_runtime.h>
#include <cuda_bf16.h>
#include <cstdint>

#define NN 50000
#define EE 800000
#define DD 64
#define TT 160                  // edge tile rows (EE/TT = 5000 exactly)
#define ET2 5000
#define NT 391                  // ceil(NN / 128)
#define KP 136                  // node-kernel padded K stride (bf16)

// ---------------- device-global scratch (no allocations allowed) ----------
__device__ float g_agg[NN * DD];
__device__ float g_agg2[NN * DD];
__device__ int   g_cnt[NN];
__device__ float g_Wc[128 * 128];
__device__ float g_Px[NN * 128];   // per-node x @ Wc[0:64] + be1
__device__ int   g_is64;

__device__ __forceinline__ int load_row(const void* eidx, int i) {
    if (g_is64) return (int)((const long long*)eidx)[i];
    return ((const int*)eidx)[i];
}

// Prologue: zero BOTH agg buffers + cnt, detect eidx dtype.
__global__ void prolog_k(const void* eidx, float* agg1, float* agg2, int* cnt) {
    int i = blockIdx.x * blockDim.x + threadIdx.x;
    if (i < NN * DD / 4) {
        ((float4*)agg1)[i] = make_float4(0.f, 0.f, 0.f, 0.f);
        ((float4*)agg2)[i] = make_float4(0.f, 0.f, 0.f, 0.f);
    }
    if (i < NN) cnt[i] = 0;
    if (i == 0) {
        const long long* p = (const long long*)eidx;
        int ok = 1;
        for (int j = 0; j < 64; j++) {
            long long v = p[j];
            if (v < 0 || v >= NN) { ok = 0; break; }
        }
        g_is64 = ok;
    }
}

// Combine We1 halves + per-node edge count (cnt zeroed by prolog).
__global__ void combine_count_k(const float* __restrict__ We1, float* __restrict__ Wc,
                                const void* __restrict__ eidx, int* cnt) {
    int i = blockIdx.x * blockDim.x + threadIdx.x;
    if (i < 128 * 128) {
        int k = i >> 7, n = i & 127;
        float v = We1[(k + 64) * 128 + n];
        if (k < 64) v += We1[k * 128 + n];
        Wc[i] = v;
    }
    if (i < EE) atomicAdd(&cnt[load_row(eidx, i)], 1);
}

// ---------------- helpers ---------------------------------------------------
__device__ __forceinline__ void split_pair(float f0, float f1, uint32_t& hi, uint32_t& lo) {
    asm("cvt.rn.bf16x2.f32 %0, %1, %2;" : "=r"(hi) : "f"(f1), "f"(f0));
    float h0 = __uint_as_float(hi << 16);
    float h1 = __uint_as_float(hi & 0xFFFF0000u);
    float r0 = f0 - h0;
    float r1 = f1 - h1;
    asm("cvt.rn.bf16x2.f32 %0, %1, %2;" : "=r"(lo) : "f"(r1), "f"(r0));
}

__device__ __forceinline__ void mma_bf16(float* d, const uint32_t* a, const uint32_t* b) {
    asm volatile(
        "mma.sync.aligned.m16n8k16.row.col.f32.bf16.bf16.f32 "
        "{%0,%1,%2,%3}, {%4,%5,%6,%7}, {%8,%9}, {%0,%1,%2,%3};"
        : "+f"(d[0]), "+f"(d[1]), "+f"(d[2]), "+f"(d[3])
        : "r"(a[0]), "r"(a[1]), "r"(a[2]), "r"(a[3]), "r"(b[0]), "r"(b[1]));
}

// ======= EDGE KERNEL: 16-row warps + fused chunking, 320 thr, 160-row tiles
// Fused: GEMM1 n-chunk (16 cols) == GEMM2 k-chunk; acc1 never materializes
// -> ~105 regs -> 10 warps/CTA x 2 CTAs = 20 warps/SM.
#define E_SA   0                  // 40KB: raw ea (160x256B) -> D2 staging
#define E_SW1  40960              // W1: 4 planes x 128 rows x 64B
#define E_SW2  73728              // W2: 8 planes x 64 rows x 64B
#define E_B2   106496             // 64 f32
#define E_RW   106752             // 160 int rows
#define E_SMEM 107392

__global__ void __launch_bounds__(320, 2)
edge_mma(const float* __restrict__ ea, const void* __restrict__ eidx,
         const float* __restrict__ Px,
         const float* __restrict__ Wc, const float* __restrict__ W2,
         const float* __restrict__ b2,
         float* __restrict__ dst, float* __restrict__ agg, int ntiles)
{
    extern __shared__ char smc[];
    float* sb2  = (float*)(smc + E_B2);
    int*   sRows = (int*)(smc + E_RW);

    const int tid = threadIdx.x;
    const int lane = tid & 31, w = tid >> 5;     // w in 0..9
    const int g = lane >> 2, qt = lane & 3;
    const int mrow0 = 16 * w + g;                // rows mrow0, mrow0+8 (<160)

    // ---- stage W1 = Wc rows 64:127 (K=64) into planes 0..3 ----
    if (tid < 256) {
        const int n = tid & 127, h = tid >> 7;
        uint32_t hi[16], lo[16];
        #pragma unroll
        for (int p = 0; p < 16; p++) {
            int k = 32 * h + 2 * p;
            split_pair(Wc[(64 + k) * 128 + n], Wc[(64 + k + 1) * 128 + n], hi[p], lo[p]);
        }
        #pragma unroll
        for (int ksl = 0; ksl < 2; ksl++)
            #pragma unroll
            for (int q = 0; q < 4; q++) {
                uint4 blk = make_uint4(hi[8 * ksl + q], hi[8 * ksl + q + 4],
                                       lo[8 * ksl + q], lo[8 * ksl + q + 4]);
                *(uint4*)(smc + E_SW1 + (2 * h + ksl) * 8192 + n * 64 + q * 16) = blk;
            }
    }
    // ---- stage W2 (64n x K=128) into planes 0..7 ----
    if (tid < 128) {
        const int n = tid & 63;
        const int kq0 = (tid >> 6) * 2;
        #pragma unroll
        for (int kq = kq0; kq < kq0 + 2; kq++) {
            uint32_t hi[16], lo[16];
            #pragma unroll
            for (int p = 0; p < 16; p++) {
                int k = 32 * kq + 2 * p;
                split_pair(W2[k * 64 + n], W2[(k + 1) * 64 + n], hi[p], lo[p]);
            }
            #pragma unroll
            for (int ksl = 0; ksl < 2; ksl++)
                #pragma unroll
                for (int q = 0; q < 4; q++) {
                    uint4 blk = make_uint4(hi[8 * ksl + q], hi[8 * ksl + q + 4],
                                           lo[8 * ksl + q], lo[8 * ksl + q + 4]);
                    *(uint4*)(smc + E_SW2 + (2 * kq + ksl) * 4096 + n * 64 + q * 16) = blk;
                }
        }
    }
    if (tid < 64) sb2[tid] = b2[tid];
    __syncthreads();

    // kernel-constant bases: GEMM loads are [base + literal]
    const char* pB1 = smc + E_SW1 + g * 64 + qt * 16;
    const char* pB2 = smc + E_SW2 + g * 64 + qt * 16;
    const char* praw0 = smc + E_SA + mrow0 * 256;
    const char* praw1 = smc + E_SA + (mrow0 + 8) * 256;
    const int x0 = mrow0 & 15, x1 = (mrow0 + 8) & 15;
    const int coff = qt >> 1, soff = 8 * (qt & 1);

    for (int tile = blockIdx.x; tile < ntiles; tile += gridDim.x) {
        const int i0 = tile * TT;

        if (tid < TT) sRows[tid] = load_row(eidx, i0 + tid);
        const int r0 = load_row(eidx, i0 + mrow0);
        const int r1 = load_row(eidx, i0 + mrow0 + 8);

        // ---- phase 1: coalesced raw copy of ea tile (XOR chunk layout) ----
        {
            const uint4* src = (const uint4*)(ea + (size_t)i0 * DD);
            #pragma unroll
            for (int p = 0; p < 8; p++) {
                int id = p * 320 + tid;
                int row = id >> 4, c = id & 15;
                *(uint4*)(smc + E_SA + (row << 8) + (((c ^ (row & 15)) & 15) << 4)) = src[id];
            }
        }

        // Px prefetch for chunk 0
        const float* pr0 = Px + (size_t)r0 * 128 + 2 * qt;
        const float* pr1 = Px + (size_t)r1 * 128 + 2 * qt;
        float pxb[2][4];
        #pragma unroll
        for (int t = 0; t < 2; t++) {
            float2 v0 = *(const float2*)(pr0 + 8 * t);
            float2 v1 = *(const float2*)(pr1 + 8 * t);
            pxb[t][0] = v0.x; pxb[t][1] = v0.y;
            pxb[t][2] = v1.x; pxb[t][3] = v1.y;
        }
        __syncthreads();

        // ---- phase 2: fragment-direct A converts (raw -> regs) ----
        uint32_t aH[4][4], aL[4][4];
        #pragma unroll
        for (int ks = 0; ks < 4; ks++) {
            int c = 4 * ks + coff;
            float2 f0 = *(const float2*)(praw0 + (((c       ^ x0) & 15) << 4) + soff);
            float2 f1 = *(const float2*)(praw1 + (((c       ^ x1) & 15) << 4) + soff);
            float2 f2 = *(const float2*)(praw0 + ((((c + 2) ^ x0) & 15) << 4) + soff);
            float2 f3 = *(const float2*)(praw1 + ((((c + 2) ^ x1) & 15) << 4) + soff);
            split_pair(f0.x, f0.y, aH[ks][0], aL[ks][0]);
            split_pair(f1.x, f1.y, aH[ks][1], aL[ks][1]);
            split_pair(f2.x, f2.y, aH[ks][2], aL[ks][2]);
            split_pair(f3.x, f3.y, aH[ks][3], aL[ks][3]);
        }
        __syncthreads();   // raw reads done -> sA reusable for D2 staging

        // ---- fused chunk loop: GEMM1 chunk -> relu/pack -> GEMM2 accumulate
        float acc2[8][4];
        #pragma unroll
        for (int nt = 0; nt < 8; nt++)
            #pragma unroll
            for (int j = 0; j < 4; j++) acc2[nt][j] = 0.f;

        #pragma unroll
        for (int c = 0; c < 8; c++) {
            float a1[2][4];
            #pragma unroll
            for (int t = 0; t < 2; t++)
                #pragma unroll
                for (int j = 0; j < 4; j++) a1[t][j] = pxb[t][j];
            if (c < 7) {
                #pragma unroll
                for (int t = 0; t < 2; t++) {
                    float2 v0 = *(const float2*)(pr0 + 8 * (2 * (c + 1) + t));
                    float2 v1 = *(const float2*)(pr1 + 8 * (2 * (c + 1) + t));
                    pxb[t][0] = v0.x; pxb[t][1] = v0.y;
                    pxb[t][2] = v1.x; pxb[t][3] = v1.y;
                }
            }
            // GEMM1 for nt = 2c, 2c+1 (full K=64, 3 split terms)
            #pragma unroll
            for (int ks = 0; ks < 4; ks++) {
                #pragma unroll
                for (int t = 0; t < 2; t++) {
                    uint4 B = *(const uint4*)(pB1 + ks * 8192 + (2 * c + t) * 512);
                    uint32_t bh[2] = {B.x, B.y}, bl[2] = {B.z, B.w};
                    mma_bf16(a1[t], aH[ks], bh);
                    mma_bf16(a1[t], aH[ks], bl);
                    mma_bf16(a1[t], aL[ks], bh);
                }
            }
            // relu + pack H fragment for GEMM2 k-step c
            uint32_t hA[4], lA[4];
            {
                float v00 = fmaxf(a1[0][0], 0.f);
                float v01 = fmaxf(a1[0][1], 0.f);
                float v02 = fmaxf(a1[0][2], 0.f);
                float v03 = fmaxf(a1[0][3], 0.f);
                float v10 = fmaxf(a1[1][0], 0.f);
                float v11 = fmaxf(a1[1][1], 0.f);
                float v12 = fmaxf(a1[1][2], 0.f);
                float v13 = fmaxf(a1[1][3], 0.f);
                split_pair(v00, v01, hA[0], lA[0]);
                split_pair(v02, v03, hA[1], lA[1]);
                split_pair(v10, v11, hA[2], lA[2]);
                split_pair(v12, v13, hA[3], lA[3]);
            }
            // GEMM2 accumulate for k-step c
            #pragma unroll
            for (int nt = 0; nt < 8; nt++) {
                uint4 B = *(const uint4*)(pB2 + c * 4096 + nt * 512);
                uint32_t bh[2] = {B.x, B.y}, bl[2] = {B.z, B.w};
                mma_bf16(acc2[nt], hA, bh);
                mma_bf16(acc2[nt], hA, bl);
                mma_bf16(acc2[nt], lA, bh);
            }
        }

        // ---- stage D2 into sA (XOR chunk layout, natural slot order) ----
        #pragma unroll
        for (int nt = 0; nt < 8; nt++) {
            int cc = 2 * nt + (qt >> 1), s = qt & 1;
            {
                int r = mrow0;
                uint32_t a = (uint32_t)(r << 8) + ((uint32_t)((cc ^ (r & 15)) & 15) << 4)
                           + ((uint32_t)s << 3);
                *(float2*)(smc + E_SA + a) = make_float2(acc2[nt][0], acc2[nt][1]);
            }
            {
                int r = mrow0 + 8;
                uint32_t a = (uint32_t)(r << 8) + ((uint32_t)((cc ^ (r & 15)) & 15) << 4)
                           + ((uint32_t)s << 3);
                *(float2*)(smc + E_SA + a) = make_float2(acc2[nt][2], acc2[nt][3]);
            }
        }
        __syncthreads();

        // ---- coalesced epilogue: red.v4 agg; dst = ea + (D2 + b2) ----
        {
            const float4* easrc = (const float4*)(ea + (size_t)i0 * DD);
            float4* dstp = (float4*)(dst + (size_t)i0 * DD);
            #pragma unroll
            for (int p = 0; p < 8; p++) {
                int id = p * 320 + tid;
                int row = id >> 4, c = id & 15;
                uint4 d = *(const uint4*)(smc + E_SA + (row << 8)
                                          + (((c ^ (row & 15)) & 15) << 4));
                float4 v;
                v.x = __uint_as_float(d.x) + sb2[4 * c + 0];
                v.y = __uint_as_float(d.y) + sb2[4 * c + 1];
                v.z = __uint_as_float(d.z) + sb2[4 * c + 2];
                v.w = __uint_as_float(d.w) + sb2[4 * c + 3];
                float* ap = agg + (size_t)sRows[row] * DD + 4 * c;
                asm volatile("red.global.add.v4.f32 [%0], {%1, %2, %3, %4};"
                             :: "l"(ap), "f"(v.x), "f"(v.y), "f"(v.z), "f"(v.w)
                             : "memory");
                float4 e = easrc[id];
                float4 o = make_float4(e.x + v.x, e.y + v.y, e.z + v.z, e.w + v.w);
                dstp[id] = o;
            }
        }
        __syncthreads();   // D2 reads done before next tile's raw copy
    }
}

// ---------------- node / px kernels -----------------------------------------
#define OFF_AH   0
#define OFF_AL   34816
#define OFF_W1H  69632
#define OFF_W1L  104448
#define OFF_W2H  139264
#define OFF_W2L  156672
#define OFF_B1   174080
#define OFF_B2   174592
#define SMEMSZ   175360

__global__ void __launch_bounds__(256, 1)
px_k(const float* __restrict__ x, const float* __restrict__ Wc,
     const float* __restrict__ be1, float* __restrict__ Px)
{
    extern __shared__ char smc[];
    uint16_t* sAh = (uint16_t*)(smc + OFF_AH);
    uint16_t* sAl = (uint16_t*)(smc + OFF_AL);
    uint16_t* sWh = (uint16_t*)(smc + OFF_W1H);
    uint16_t* sWl = (uint16_t*)(smc + OFF_W1L);
    float*    sb1 = (float*)(smc + OFF_B1);

    const int tid = threadIdx.x;
    const int lane = tid & 31, w = tid >> 5;
    const int g = lane >> 2, qt = lane & 3;
    const int wm = w >> 1, wn = w & 1;

    {
        int n = tid & 127, k0 = (tid >> 7) * 32;
        for (int k = k0; k < k0 + 32; k += 2) {
            uint32_t hi, lo;
            split_pair(Wc[k * 128 + n], Wc[(k + 1) * 128 + n], hi, lo);
            *(uint32_t*)&sWh[n * KP + k] = hi;
            *(uint32_t*)&sWl[n * KP + k] = lo;
        }
    }
    if (tid < 128) sb1[tid] = be1[tid];
    __syncthreads();

    for (int tile = blockIdx.x; tile < NT; tile += gridDim.x) {
        const int i0 = tile * 128;
        {
            const int m = tid & 127, ch = (tid >> 7) * 32;
            const int gi = i0 + m;
            const bool valid = gi < NN;
            const float* src = x + (size_t)(valid ? gi : 0) * DD + ch;
            #pragma unroll
            for (int c = 0; c < 32; c += 8) {
                float4 f0, f1;
                if (valid) { f0 = *(const float4*)(src + c); f1 = *(const float4*)(src + c + 4); }
                else { f0 = make_float4(0,0,0,0); f1 = f0; }
                uint32_t hw[4], lw[4];
                split_pair(f0.x, f0.y, hw[0], lw[0]);
                split_pair(f0.z, f0.w, hw[1], lw[1]);
                split_pair(f1.x, f1.y, hw[2], lw[2]);
                split_pair(f1.z, f1.w, hw[3], lw[3]);
                int e = m * KP + ch + c;
                *(uint4*)&sAh[e] = *(uint4*)hw;
                *(uint4*)&sAl[e] = *(uint4*)lw;
            }
        }
        __syncthreads();

        float acc[2][8][4];
        #pragma unroll
        for (int mt = 0; mt < 2; mt++)
            #pragma unroll
            for (int nt = 0; nt < 8; nt++)
                #pragma unroll
                for (int j = 0; j < 4; j++) acc[mt][nt][j] = 0.f;

        #pragma unroll
        for (int ks = 0; ks < 4; ks++) {
            const int kb = ks * 16 + 2 * qt;
            uint32_t ah[2][4], al[2][4];
            #pragma unroll
            for (int mt = 0; mt < 2; mt++) {
                int e = (wm * 32 + mt * 16 + g) * KP + kb;
                ah[mt][0] = *(const uint32_t*)&sAh[e];
                ah[mt][1] = *(const uint32_t*)&sAh[e + 8 * KP];
                ah[mt][2] = *(const uint32_t*)&sAh[e + 8];
                ah[mt][3] = *(const uint32_t*)&sAh[e + 8 * KP + 8];
                al[mt][0] = *(const uint32_t*)&sAl[e];
                al[mt][1] = *(const uint32_t*)&sAl[e + 8 * KP];
                al[mt][2] = *(const uint32_t*)&sAl[e + 8];
                al[mt][3] = *(const uint32_t*)&sAl[e + 8 * KP + 8];
            }
            #pragma unroll
            for (int nt = 0; nt < 8; nt++) {
                int e = (wn * 64 + nt * 8 + g) * KP + kb;
                uint32_t bh[2], bl[2];
                bh[0] = *(const uint32_t*)&sWh[e];
                bh[1] = *(const uint32_t*)&sWh[e + 8];
                bl[0] = *(const uint32_t*)&sWl[e];
                bl[1] = *(const uint32_t*)&sWl[e + 8];
                mma_bf16(acc[0][nt], ah[0], bh);
                mma_bf16(acc[1][nt], ah[1], bh);
                mma_bf16(acc[0][nt], ah[0], bl);
                mma_bf16(acc[1][nt], ah[1], bl);
                mma_bf16(acc[0][nt], al[0], bh);
                mma_bf16(acc[1][nt], al[1], bh);
            }
        }

        #pragma unroll
        for (int mt = 0; mt < 2; mt++)
            #pragma unroll
            for (int nt = 0; nt < 8; nt++) {
                int rl = wm * 32 + mt * 16 + g;
                int col = wn * 64 + nt * 8 + 2 * qt;
                #pragma unroll
                for (int rh = 0; rh < 2; rh++) {
                    int gi = i0 + rl + rh * 8;
                    if (gi >= NN) continue;
                    float2 v = make_float2(acc[mt][nt][rh * 2] + sb1[col],
                                           acc[mt][nt][rh * 2 + 1] + sb1[col + 1]);
                    *(float2*)&Px[(size_t)gi * 128 + col] = v;
                }
            }
        __syncthreads();
    }
}

__global__ void __launch_bounds__(256, 1)
node_mma(const float* __restrict__ x_src, const float* __restrict__ a_src,
         const float* __restrict__ W1, const float* __restrict__ b1,
         const float* __restrict__ W2, const float* __restrict__ b2,
         float* __restrict__ dst, const int* __restrict__ cnt, int count)
{
    extern __shared__ char smc[];
    uint16_t* sAh  = (uint16_t*)(smc + OFF_AH);
    uint16_t* sAl  = (uint16_t*)(smc + OFF_AL);
    uint16_t* sW1h = (uint16_t*)(smc + OFF_W1H);
    uint16_t* sW1l = (uint16_t*)(smc + OFF_W1L);
    uint16_t* sW2h = (uint16_t*)(smc + OFF_W2H);
    uint16_t* sW2l = (uint16_t*)(smc + OFF_W2L);
    float*    sb1  = (float*)(smc + OFF_B1);
    float*    sb2  = (float*)(smc + OFF_B2);

    const int tid = threadIdx.x;
    const int lane = tid & 31, w = tid >> 5;
    const int g = lane >> 2, qt = lane & 3;
    const int wm = w >> 1, wn = w & 1;

    {
        int n = tid & 127, k0 = (tid >> 7) * 64;
        for (int k = k0; k < k0 + 64; k += 2) {
            uint32_t hi, lo;
            split_pair(W1[k * 128 + n], W1[(k + 1) * 128 + n], hi, lo);
            *(uint32_t*)&sW1h[n * KP + k] = hi;
            *(uint32_t*)&sW1l[n * KP + k] = lo;
        }
    }
    {
        int n = tid & 63, k0 = (tid >> 6) * 32;
        for (int k = k0; k < k0 + 32; k += 2) {
            uint32_t hi, lo;
            split_pair(W2[k * 64 + n], W2[(k + 1) * 64 + n], hi, lo);
            *(uint32_t*)&sW2h[n * KP + k] = hi;
            *(uint32_t*)&sW2l[n * KP + k] = lo;
        }
    }
    if (tid < 128) sb1[tid] = b1[tid];
    if (tid < 64)  sb2[tid] = b2[tid];
    __syncthreads();

    for (int tile = blockIdx.x; tile < NT; tile += gridDim.x) {
        const int i0 = tile * 128;
        {
            const int m = tid & 127, half = tid >> 7;
            const int gi = i0 + m;
            const bool valid = gi < count;
            const float* src;
            float scale = 1.0f;
            bool doscale = false;
            if (half == 0) {
                src = x_src + (size_t)(valid ? gi : 0) * DD;
            } else {
                src = a_src + (size_t)(valid ? gi : 0) * DD;
                scale = valid ? (1.0f / fmaxf((float)cnt[gi], 1.0f)) : 0.0f;
                doscale = true;
            }
            #pragma unroll
            for (int c = 0; c < 64; c += 8) {
                float4 f0 = *(const float4*)(src + c);
                float4 f1 = *(const float4*)(src + c + 4);
                if (doscale) {
                    f0.x *= scale; f0.y *= scale; f0.z *= scale; f0.w *= scale;
                    f1.x *= scale; f1.y *= scale; f1.z *= scale; f1.w *= scale;
                }
                uint32_t hw[4], lw[4];
                split_pair(f0.x, f0.y, hw[0], lw[0]);
                split_pair(f0.z, f0.w, hw[1], lw[1]);
                split_pair(f1.x, f1.y, hw[2], lw[2]);
                split_pair(f1.z, f1.w, hw[3], lw[3]);
                int e = m * KP + half * 64 + c;
                *(uint4*)&sAh[e] = *(uint4*)hw;
                *(uint4*)&sAl[e] = *(uint4*)lw;
            }
        }
        __syncthreads();

        float acc[2][8][4];
        #pragma unroll
        for (int mt = 0; mt < 2; mt++)
            #pragma unroll
            for (int nt = 0; nt < 8; nt++)
                #pragma unroll
                for (int j = 0; j < 4; j++) acc[mt][nt][j] = 0.f;

        #pragma unroll
        for (int ks = 0; ks < 8; ks++) {
            const int kb = ks * 16 + 2 * qt;
            uint32_t ah[2][4], al[2][4];
            #pragma unroll
            for (int mt = 0; mt < 2; mt++) {
                int e = (wm * 32 + mt * 16 + g) * KP + kb;
                ah[mt][0] = *(const uint32_t*)&sAh[e];
                ah[mt][1] = *(const uint32_t*)&sAh[e + 8 * KP];
                ah[mt][2] = *(const uint32_t*)&sAh[e + 8];
                ah[mt][3] = *(const uint32_t*)&sAh[e + 8 * KP + 8];
                al[mt][0] = *(const uint32_t*)&sAl[e];
                al[mt][1] = *(const uint32_t*)&sAl[e + 8 * KP];
                al[mt][2] = *(const uint32_t*)&sAl[e + 8];
                al[mt][3] = *(const uint32_t*)&sAl[e + 8 * KP + 8];
            }
            #pragma unroll
            for (int nt = 0; nt < 8; nt++) {
                int e = (wn * 64 + nt * 8 + g) * KP + kb;
                uint32_t bh[2], bl[2];
                bh[0] = *(const uint32_t*)&sW1h[e];
                bh[1] = *(const uint32_t*)&sW1h[e + 8];
                bl[0] = *(const uint32_t*)&sW1l[e];
                bl[1] = *(const uint32_t*)&sW1l[e + 8];
                mma_bf16(acc[0][nt], ah[0], bh);
                mma_bf16(acc[1][nt], ah[1], bh);
                mma_bf16(acc[0][nt], ah[0], bl);
                mma_bf16(acc[1][nt], ah[1], bl);
                mma_bf16(acc[0][nt], al[0], bh);
                mma_bf16(acc[1][nt], al[1], bh);
            }
        }
        __syncthreads();

        #pragma unroll
        for (int mt = 0; mt < 2; mt++)
            #pragma unroll
            for (int nt = 0; nt < 8; nt++) {
                int row = wm * 32 + mt * 16 + g;
                int col = wn * 64 + nt * 8 + 2 * qt;
                float v0 = fmaxf(acc[mt][nt][0] + sb1[col], 0.f);
                float v1 = fmaxf(acc[mt][nt][1] + sb1[col + 1], 0.f);
                float v2 = fmaxf(acc[mt][nt][2] + sb1[col], 0.f);
                float v3 = fmaxf(acc[mt][nt][3] + sb1[col + 1], 0.f);
                uint32_t hi, lo;
                split_pair(v0, v1, hi, lo);
                *(uint32_t*)&sAh[row * KP + col] = hi;
                *(uint32_t*)&sAl[row * KP + col] = lo;
                split_pair(v2, v3, hi, lo);
                *(uint32_t*)&sAh[(row + 8) * KP + col] = hi;
                *(uint32_t*)&sAl[(row + 8) * KP + col] = lo;
            }
        __syncthreads();

        float acc2[2][4][4];
        #pragma unroll
        for (int mt = 0; mt < 2; mt++)
            #pragma unroll
            for (int nt = 0; nt < 4; nt++)
                #pragma unroll
                for (int j = 0; j < 4; j++) acc2[mt][nt][j] = 0.f;

        #pragma unroll
        for (int ks = 0; ks < 8; ks++) {
            const int kb = ks * 16 + 2 * qt;
            uint32_t ah[2][4], al[2][4];
            #pragma unroll
            for (int mt = 0; mt < 2; mt++) {
                int e = (wm * 32 + mt * 16 + g) * KP + kb;
                ah[mt][0] = *(const uint32_t*)&sAh[e];
                ah[mt][1] = *(const uint32_t*)&sAh[e + 8 * KP];
                ah[mt][2] = *(const uint32_t*)&sAh[e + 8];
                ah[mt][3] = *(const uint32_t*)&sAh[e + 8 * KP + 8];
                al[mt][0] = *(const uint32_t*)&sAl[e];
                al[mt][1] = *(const uint32_t*)&sAl[e + 8 * KP];
                al[mt][2] = *(const uint32_t*)&sAl[e + 8];
                al[mt][3] = *(const uint32_t*)&sAl[e + 8 * KP + 8];
            }
            #pragma unroll
            for (int nt = 0; nt < 4; nt++) {
                int e = (wn * 32 + nt * 8 + g) * KP + kb;
                uint32_t bh[2], bl[2];
                bh[0] = *(const uint32_t*)&sW2h[e];
                bh[1] = *(const uint32_t*)&sW2h[e + 8];
                bl[0] = *(const uint32_t*)&sW2l[e];
                bl[1] = *(const uint32_t*)&sW2l[e + 8];
                mma_bf16(acc2[0][nt], ah[0], bh);
                mma_bf16(acc2[1][nt], ah[1], bh);
                mma_bf16(acc2[0][nt], ah[0], bl);
                mma_bf16(acc2[1][nt], ah[1], bl);
                mma_bf16(acc2[0][nt], al[0], bh);
                mma_bf16(acc2[1][nt], al[1], bh);
            }
        }

        #pragma unroll
        for (int mt = 0; mt < 2; mt++)
            #pragma unroll
            for (int nt = 0; nt < 4; nt++) {
                int rl = wm * 32 + mt * 16 + g;
                int col = wn * 32 + nt * 8 + 2 * qt;
                #pragma unroll
                for (int rh = 0; rh < 2; rh++) {
                    int row = rl + rh * 8;
                    int gi = i0 + row;
                    if (gi >= count) continue;
                    float vx = acc2[mt][nt][rh * 2 + 0] + sb2[col];
                    float vy = acc2[mt][nt][rh * 2 + 1] + sb2[col + 1];
                    float2 rv = *(const float2*)(x_src + (size_t)gi * DD + col);
                    *(float2*)(dst + (size_t)gi * DD + col) =
                        make_float2(rv.x + vx, rv.y + vy);
                }
            }
        __syncthreads();
    }
}

extern "C" void kernel_launch(void* const* d_in, const int* in_sizes, int n_in,
                              void* d_out, int out_size)
{
    const float* x   = (const float*)d_in[0];
    const float* ea  = (const float*)d_in[1];
    const float* We1 = (const float*)d_in[2];
    const float* be1 = (const float*)d_in[3];
    const float* We2 = (const float*)d_in[4];
    const float* be2 = (const float*)d_in[5];
    const float* Wn1 = (const float*)d_in[6];
    const float* bn1 = (const float*)d_in[7];
    const float* Wn2 = (const float*)d_in[8];
    const float* bn2 = (const float*)d_in[9];
    const void*  eidx = d_in[10];

    float* out_x  = (float*)d_out;
    float* out_ea = (float*)d_out + (size_t)NN * DD;

    float *agg, *agg2, *Wc, *Px;
    int* cnt;
    cudaGetSymbolAddress((void**)&agg,  g_agg);
    cudaGetSymbolAddress((void**)&agg2, g_agg2);
    cudaGetSymbolAddress((void**)&cnt,  g_cnt);
    cudaGetSymbolAddress((void**)&Wc,   g_Wc);
    cudaGetSymbolAddress((void**)&Px,   g_Px);

    cudaFuncSetAttribute(edge_mma, cudaFuncAttributeMaxDynamicSharedMemorySize, E_SMEM);
    cudaFuncSetAttribute(node_mma, cudaFuncAttributeMaxDynamicSharedMemorySize, SMEMSZ);
    cudaFuncSetAttribute(px_k,     cudaFuncAttributeMaxDynamicSharedMemorySize, SMEMSZ);

    int smcount = 148;
    cudaDeviceGetAttribute(&smcount, cudaDevAttrMultiProcessorCount, 0);
    int ge = 2 * smcount < ET2 ? 2 * smcount : ET2;
    int gn = smcount < NT ? smcount : NT;

    // Edge kernel stays at my launch index 3 (profiled by ncu -s 5 -c 1).
    prolog_k<<<(NN * DD / 4 + 255) / 256, 256>>>(eidx, agg, agg2, cnt);      // 0
    combine_count_k<<<(EE + 255) / 256, 256>>>(We1, Wc, eidx, cnt);          // 1
    px_k<<<gn, 256, SMEMSZ>>>(x, Wc, be1, Px);                               // 2
    edge_mma<<<ge, 320, E_SMEM>>>(ea, eidx, Px, Wc, We2, be2,                // 3 <- profiled
                                  out_ea, agg, ET2);
    node_mma<<<gn, 256, SMEMSZ>>>(x, agg, Wn1, bn1, Wn2, bn2,                // 4
                                  out_x, cnt, NN);

    // iteration 2 (agg2 pre-zeroed in prolog -> no mid-stream zero pass)
    px_k<<<gn, 256, SMEMSZ>>>(out_x, Wc, be1, Px);                           // 5
    edge_mma<<<ge, 320, E_SMEM>>>(out_ea, eidx, Px, Wc, We2, be2,            // 6
                                  out_ea, agg2, ET2);
    node_mma<<<gn, 256, SMEMSZ>>>(out_x, agg2, Wn1, bn1, Wn2, bn2,           // 7
                                  out_x, cnt, NN);
}

// round 16
// speedup vs baseline: 1.1781x; 1.1781x over previous
#include <cuda_runtime.h>
#include <cuda_bf16.h>
#include <cstdint>

#define NN 50000
#define EE 800000
#define DD 64
#define ET 6250                 // EE / 128
#define NT 391                  // ceil(NN / 128)
#define KP 136                  // node-kernel padded K stride (bf16)

// ---------------- device-global scratch (no allocations allowed) ----------
__device__ float g_agg[NN * DD];
__device__ float g_agg2[NN * DD];
__device__ int   g_cnt[NN];
__device__ float g_Wc[128 * 128];
__device__ float g_Px[NN * 128];   // per-node x @ Wc[0:64] + be1
__device__ int   g_is64;

__device__ __forceinline__ int load_row(const void* eidx, int i) {
    if (g_is64) return (int)((const long long*)eidx)[i];
    return ((const int*)eidx)[i];
}

// Prologue: zero BOTH agg buffers + cnt, detect eidx dtype.
__global__ void prolog_k(const void* eidx, float* agg1, float* agg2, int* cnt) {
    int i = blockIdx.x * blockDim.x + threadIdx.x;
    if (i < NN * DD / 4) {
        ((float4*)agg1)[i] = make_float4(0.f, 0.f, 0.f, 0.f);
        ((float4*)agg2)[i] = make_float4(0.f, 0.f, 0.f, 0.f);
    }
    if (i < NN) cnt[i] = 0;
    if (i == 0) {
        const long long* p = (const long long*)eidx;
        int ok = 1;
        for (int j = 0; j < 64; j++) {
            long long v = p[j];
            if (v < 0 || v >= NN) { ok = 0; break; }
        }
        g_is64 = ok;
    }
}

// Combine We1 halves + per-node edge count (cnt zeroed by prolog).
__global__ void combine_count_k(const float* __restrict__ We1, float* __restrict__ Wc,
                                const void* __restrict__ eidx, int* cnt) {
    int i = blockIdx.x * blockDim.x + threadIdx.x;
    if (i < 128 * 128) {
        int k = i >> 7, n = i & 127;
        float v = We1[(k + 64) * 128 + n];
        if (k < 64) v += We1[k * 128 + n];
        Wc[i] = v;
    }
    if (i < EE) atomicAdd(&cnt[load_row(eidx, i)], 1);
}

// ---------------- helpers ---------------------------------------------------
__device__ __forceinline__ void split_pair(float f0, float f1, uint32_t& hi, uint32_t& lo) {
    asm("cvt.rn.bf16x2.f32 %0, %1, %2;" : "=r"(hi) : "f"(f1), "f"(f0));
    float h0 = __uint_as_float(hi << 16);
    float h1 = __uint_as_float(hi & 0xFFFF0000u);
    float r0 = f0 - h0;
    float r1 = f1 - h1;
    asm("cvt.rn.bf16x2.f32 %0, %1, %2;" : "=r"(lo) : "f"(r1), "f"(r0));
}

__device__ __forceinline__ void mma_bf16(float* d, const uint32_t* a, const uint32_t* b) {
    asm volatile(
        "mma.sync.aligned.m16n8k16.row.col.f32.bf16.bf16.f32 "
        "{%0,%1,%2,%3}, {%4,%5,%6,%7}, {%8,%9}, {%0,%1,%2,%3};"
        : "+f"(d[0]), "+f"(d[1]), "+f"(d[2]), "+f"(d[3])
        : "r"(a[0]), "r"(a[1]), "r"(a[2]), "r"(a[3]), "r"(b[0]), "r"(b[1]));
}

// ================= EDGE KERNEL (round-13 structure, per-ks H pack) =========
#define E_SA   0                  // 32KB: raw ea -> (later) D2 staging
#define E_SW1  32768              // W1: 4 planes x 128 rows x 64B
#define E_SW2  65536              // W2: 8 planes x 64 rows x 64B
#define E_B2   98304              // 64 f32
#define E_RW   98560              // 128 int rows
#define E_SMEM 99072

__global__ void __launch_bounds__(256, 2)
edge_mma(const float* __restrict__ ea, const void* __restrict__ eidx,
         const float* __restrict__ Px,
         const float* __restrict__ Wc, const float* __restrict__ W2,
         const float* __restrict__ b2,
         float* __restrict__ dst, float* __restrict__ agg, int ntiles)
{
    extern __shared__ char smc[];
    float* sb2  = (float*)(smc + E_B2);
    int*   sRows = (int*)(smc + E_RW);

    const int tid = threadIdx.x;
    const int lane = tid & 31, w = tid >> 5;
    const int g = lane >> 2, qt = lane & 3;
    const int mrow0 = 16 * w + g;

    // ---- stage W1 = Wc rows 64:127 (K=64) into planes 0..3 ----
    {
        const int n = tid & 127, h = tid >> 7;
        uint32_t hi[16], lo[16];
        #pragma unroll
        for (int p = 0; p < 16; p++) {
            int k = 32 * h + 2 * p;
            split_pair(Wc[(64 + k) * 128 + n], Wc[(64 + k + 1) * 128 + n], hi[p], lo[p]);
        }
        #pragma unroll
        for (int ksl = 0; ksl < 2; ksl++)
            #pragma unroll
            for (int q = 0; q < 4; q++) {
                uint4 blk = make_uint4(hi[8 * ksl + q], hi[8 * ksl + q + 4],
                                       lo[8 * ksl + q], lo[8 * ksl + q + 4]);
                *(uint4*)(smc + E_SW1 + (2 * h + ksl) * 8192 + n * 64 + q * 16) = blk;
            }
    }
    // ---- stage W2 (64n x K=128) into planes 0..7 ----
    {
        const int n = tid & 63, kq = tid >> 6;
        uint32_t hi[16], lo[16];
        #pragma unroll
        for (int p = 0; p < 16; p++) {
            int k = 32 * kq + 2 * p;
            split_pair(W2[k * 64 + n], W2[(k + 1) * 64 + n], hi[p], lo[p]);
        }
        #pragma unroll
        for (int ksl = 0; ksl < 2; ksl++)
            #pragma unroll
            for (int q = 0; q < 4; q++) {
                uint4 blk = make_uint4(hi[8 * ksl + q], hi[8 * ksl + q + 4],
                                       lo[8 * ksl + q], lo[8 * ksl + q + 4]);
                *(uint4*)(smc + E_SW2 + (2 * kq + ksl) * 4096 + n * 64 + q * 16) = blk;
            }
    }
    if (tid < 64) sb2[tid] = b2[tid];
    __syncthreads();

    // kernel-constant base pointers for B loads: [base + literal]
    const char* pB1 = smc + E_SW1 + g * 64 + qt * 16;
    const char* pB2 = smc + E_SW2 + g * 64 + qt * 16;
    const char* praw0 = smc + E_SA + mrow0 * 256;
    const char* praw1 = smc + E_SA + (mrow0 + 8) * 256;
    const int x0 = mrow0 & 15, x1 = (mrow0 + 8) & 15;
    const int coff = qt >> 1, soff = 8 * (qt & 1);

    for (int tile = blockIdx.x; tile < ntiles; tile += gridDim.x) {
        const int i0 = tile * 128;

        if (tid < 128) sRows[tid] = load_row(eidx, i0 + tid);
        const int r0 = load_row(eidx, i0 + mrow0);
        const int r1 = load_row(eidx, i0 + mrow0 + 8);

        // ---- phase 1: coalesced raw copy of ea tile (XOR chunk layout) ----
        {
            const uint4* src = (const uint4*)(ea + (size_t)i0 * DD);
            #pragma unroll
            for (int p = 0; p < 8; p++) {
                int id = p * 256 + tid;
                int row = id >> 4, c = id & 15;
                *(uint4*)(smc + E_SA + (row << 8) + (((c ^ (row & 15)) & 15) << 4)) = src[id];
            }
        }
        __syncthreads();

        // ---- phase 2: fragment-direct convert (raw -> registers) ----
        uint32_t aH[4][4], aL[4][4];
        #pragma unroll
        for (int ks = 0; ks < 4; ks++) {
            int c = 4 * ks + coff;
            float2 f0 = *(const float2*)(praw0 + (((c     ^ x0) & 15) << 4) + soff);
            float2 f1 = *(const float2*)(praw1 + (((c     ^ x1) & 15) << 4) + soff);
            float2 f2 = *(const float2*)(praw0 + ((((c+2) ^ x0) & 15) << 4) + soff);
            float2 f3 = *(const float2*)(praw1 + ((((c+2) ^ x1) & 15) << 4) + soff);
            split_pair(f0.x, f0.y, aH[ks][0], aL[ks][0]);
            split_pair(f1.x, f1.y, aH[ks][1], aL[ks][1]);
            split_pair(f2.x, f2.y, aH[ks][2], aL[ks][2]);
            split_pair(f3.x, f3.y, aH[ks][3], aL[ks][3]);
        }

        // ---- init acc1 from Px gather (be1 folded into Px) ----
        float acc1[16][4];
        {
            const float* pr0 = Px + (size_t)r0 * 128 + 2 * qt;
            const float* pr1 = Px + (size_t)r1 * 128 + 2 * qt;
            #pragma unroll
            for (int nt = 0; nt < 16; nt++) {
                float2 v0 = *(const float2*)(pr0 + 8 * nt);
                float2 v1 = *(const float2*)(pr1 + 8 * nt);
                acc1[nt][0] = v0.x; acc1[nt][1] = v0.y;
                acc1[nt][2] = v1.x; acc1[nt][3] = v1.y;
            }
        }
        __syncthreads();   // all raw reads done -> sA reusable for D2 staging

        // ---- GEMM1: acc1 += ea @ W1 (K=64, 3 split terms), A in regs ----
        #pragma unroll
        for (int ks = 0; ks < 4; ks++) {
            #pragma unroll
            for (int nt = 0; nt < 16; nt++) {
                uint4 B = *(const uint4*)(pB1 + ks * 8192 + nt * 512);
                uint32_t bh[2] = {B.x, B.y}, bl[2] = {B.z, B.w};
                mma_bf16(acc1[nt], aH[ks], bh);
                mma_bf16(acc1[nt], aH[ks], bl);
                mma_bf16(acc1[nt], aL[ks], bh);
            }
        }

        // ---- GEMM2: per-ks pack (relu fused) then 8 MMAs; acc1 dies per-ks
        float acc2[8][4];
        #pragma unroll
        for (int nt = 0; nt < 8; nt++)
            #pragma unroll
            for (int j = 0; j < 4; j++) acc2[nt][j] = 0.f;

        #pragma unroll
        for (int ks = 0; ks < 8; ks++) {
            uint32_t hA[4], lA[4];
            float v00 = fmaxf(acc1[2 * ks][0], 0.f);
            float v01 = fmaxf(acc1[2 * ks][1], 0.f);
            float v02 = fmaxf(acc1[2 * ks][2], 0.f);
            float v03 = fmaxf(acc1[2 * ks][3], 0.f);
            float v10 = fmaxf(acc1[2 * ks + 1][0], 0.f);
            float v11 = fmaxf(acc1[2 * ks + 1][1], 0.f);
            float v12 = fmaxf(acc1[2 * ks + 1][2], 0.f);
            float v13 = fmaxf(acc1[2 * ks + 1][3], 0.f);
            split_pair(v00, v01, hA[0], lA[0]);
            split_pair(v02, v03, hA[1], lA[1]);
            split_pair(v10, v11, hA[2], lA[2]);
            split_pair(v12, v13, hA[3], lA[3]);
            #pragma unroll
            for (int nt = 0; nt < 8; nt++) {
                uint4 B = *(const uint4*)(pB2 + ks * 4096 + nt * 512);
                uint32_t bh[2] = {B.x, B.y}, bl[2] = {B.z, B.w};
                mma_bf16(acc2[nt], hA, bh);
                mma_bf16(acc2[nt], hA, bl);
                mma_bf16(acc2[nt], lA, bh);
            }
        }

        // ---- stage D2 into sA (XOR chunk layout, natural slot order) ----
        #pragma unroll
        for (int nt = 0; nt < 8; nt++) {
            int c = 2 * nt + (qt >> 1), s = qt & 1;
            {
                int r = mrow0;
                uint32_t a = (uint32_t)(r << 8) + ((uint32_t)((c ^ (r & 15)) & 15) << 4)
                           + ((uint32_t)s << 3);
                *(float2*)(smc + E_SA + a) = make_float2(acc2[nt][0], acc2[nt][1]);
            }
            {
                int r = mrow0 + 8;
                uint32_t a = (uint32_t)(r << 8) + ((uint32_t)((c ^ (r & 15)) & 15) << 4)
                           + ((uint32_t)s << 3);
                *(float2*)(smc + E_SA + a) = make_float2(acc2[nt][2], acc2[nt][3]);
            }
        }
        __syncthreads();

        // ---- coalesced epilogue: red.v4 agg; dst = ea + (D2 + b2) ----
        {
            const float4* easrc = (const float4*)(ea + (size_t)i0 * DD);
            float4* dstp = (float4*)(dst + (size_t)i0 * DD);
            #pragma unroll
            for (int p = 0; p < 8; p++) {
                int id = p * 256 + tid;
                int row = id >> 4, c = id & 15;
                uint4 d = *(const uint4*)(smc + E_SA + (row << 8)
                                          + (((c ^ (row & 15)) & 15) << 4));
                float4 v;
                v.x = __uint_as_float(d.x) + sb2[4 * c + 0];
                v.y = __uint_as_float(d.y) + sb2[4 * c + 1];
                v.z = __uint_as_float(d.z) + sb2[4 * c + 2];
                v.w = __uint_as_float(d.w) + sb2[4 * c + 3];
                float* ap = agg + (size_t)sRows[row] * DD + 4 * c;
                asm volatile("red.global.add.v4.f32 [%0], {%1, %2, %3, %4};"
                             :: "l"(ap), "f"(v.x), "f"(v.y), "f"(v.z), "f"(v.w)
                             : "memory");
                float4 e = easrc[id];
                float4 o = make_float4(e.x + v.x, e.y + v.y, e.z + v.z, e.w + v.w);
                dstp[id] = o;
            }
        }
        __syncthreads();   // D2 reads done before next tile's raw copy
    }
}

// ---------------- node / px kernels ----------------------------------------
#define OFF_AH   0
#define OFF_AL   34816
#define OFF_W1H  69632
#define OFF_W1L  104448
#define OFF_W2H  139264
#define OFF_W2L  156672
#define OFF_B1   174080
#define OFF_B2   174592
#define SMEMSZ   175360

__global__ void __launch_bounds__(256, 1)
px_k(const float* __restrict__ x, const float* __restrict__ Wc,
     const float* __restrict__ be1, float* __restrict__ Px)
{
    extern __shared__ char smc[];
    uint16_t* sAh = (uint16_t*)(smc + OFF_AH);
    uint16_t* sAl = (uint16_t*)(smc + OFF_AL);
    uint16_t* sWh = (uint16_t*)(smc + OFF_W1H);
    uint16_t* sWl = (uint16_t*)(smc + OFF_W1L);
    float*    sb1 = (float*)(smc + OFF_B1);

    const int tid = threadIdx.x;
    const int lane = tid & 31, w = tid >> 5;
    const int g = lane >> 2, qt = lane & 3;
    const int wm = w >> 1, wn = w & 1;

    {
        int n = tid & 127, k0 = (tid >> 7) * 32;
        for (int k = k0; k < k0 + 32; k += 2) {
            uint32_t hi, lo;
            split_pair(Wc[k * 128 + n], Wc[(k + 1) * 128 + n], hi, lo);
            *(uint32_t*)&sWh[n * KP + k] = hi;
            *(uint32_t*)&sWl[n * KP + k] = lo;
        }
    }
    if (tid < 128) sb1[tid] = be1[tid];
    __syncthreads();

    for (int tile = blockIdx.x; tile < NT; tile += gridDim.x) {
        const int i0 = tile * 128;
        {
            const int m = tid & 127, ch = (tid >> 7) * 32;
            const int gi = i0 + m;
            const bool valid = gi < NN;
            const float* src = x + (size_t)(valid ? gi : 0) * DD + ch;
            #pragma unroll
            for (int c = 0; c < 32; c += 8) {
                float4 f0, f1;
                if (valid) { f0 = *(const float4*)(src + c); f1 = *(const float4*)(src + c + 4); }
                else { f0 = make_float4(0,0,0,0); f1 = f0; }
                uint32_t hw[4], lw[4];
                split_pair(f0.x, f0.y, hw[0], lw[0]);
                split_pair(f0.z, f0.w, hw[1], lw[1]);
                split_pair(f1.x, f1.y, hw[2], lw[2]);
                split_pair(f1.z, f1.w, hw[3], lw[3]);
                int e = m * KP + ch + c;
                *(uint4*)&sAh[e] = *(uint4*)hw;
                *(uint4*)&sAl[e] = *(uint4*)lw;
            }
        }
        __syncthreads();

        float acc[2][8][4];
        #pragma unroll
        for (int mt = 0; mt < 2; mt++)
            #pragma unroll
            for (int nt = 0; nt < 8; nt++)
                #pragma unroll
                for (int j = 0; j < 4; j++) acc[mt][nt][j] = 0.f;

        #pragma unroll
        for (int ks = 0; ks < 4; ks++) {
            const int kb = ks * 16 + 2 * qt;
            uint32_t ah[2][4], al[2][4];
            #pragma unroll
            for (int mt = 0; mt < 2; mt++) {
                int e = (wm * 32 + mt * 16 + g) * KP + kb;
                ah[mt][0] = *(const uint32_t*)&sAh[e];
                ah[mt][1] = *(const uint32_t*)&sAh[e + 8 * KP];
                ah[mt][2] = *(const uint32_t*)&sAh[e + 8];
                ah[mt][3] = *(const uint32_t*)&sAh[e + 8 * KP + 8];
                al[mt][0] = *(const uint32_t*)&sAl[e];
                al[mt][1] = *(const uint32_t*)&sAl[e + 8 * KP];
                al[mt][2] = *(const uint32_t*)&sAl[e + 8];
                al[mt][3] = *(const uint32_t*)&sAl[e + 8 * KP + 8];
            }
            #pragma unroll
            for (int nt = 0; nt < 8; nt++) {
                int e = (wn * 64 + nt * 8 + g) * KP + kb;
                uint32_t bh[2], bl[2];
                bh[0] = *(const uint32_t*)&sWh[e];
                bh[1] = *(const uint32_t*)&sWh[e + 8];
                bl[0] = *(const uint32_t*)&sWl[e];
                bl[1] = *(const uint32_t*)&sWl[e + 8];
                mma_bf16(acc[0][nt], ah[0], bh);
                mma_bf16(acc[1][nt], ah[1], bh);
                mma_bf16(acc[0][nt], ah[0], bl);
                mma_bf16(acc[1][nt], ah[1], bl);
                mma_bf16(acc[0][nt], al[0], bh);
                mma_bf16(acc[1][nt], al[1], bh);
            }
        }

        #pragma unroll
        for (int mt = 0; mt < 2; mt++)
            #pragma unroll
            for (int nt = 0; nt < 8; nt++) {
                int rl = wm * 32 + mt * 16 + g;
                int col = wn * 64 + nt * 8 + 2 * qt;
                #pragma unroll
                for (int rh = 0; rh < 2; rh++) {
                    int gi = i0 + rl + rh * 8;
                    if (gi >= NN) continue;
                    float2 v = make_float2(acc[mt][nt][rh * 2] + sb1[col],
                                           acc[mt][nt][rh * 2 + 1] + sb1[col + 1]);
                    *(float2*)&Px[(size_t)gi * 128 + col] = v;
                }
            }
        __syncthreads();
    }
}

__global__ void __launch_bounds__(256, 1)
node_mma(const float* __restrict__ x_src, const float* __restrict__ a_src,
         const float* __restrict__ W1, const float* __restrict__ b1,
         const float* __restrict__ W2, const float* __restrict__ b2,
         float* __restrict__ dst, const int* __restrict__ cnt, int count)
{
    extern __shared__ char smc[];
    uint16_t* sAh  = (uint16_t*)(smc + OFF_AH);
    uint16_t* sAl  = (uint16_t*)(smc + OFF_AL);
    uint16_t* sW1h = (uint16_t*)(smc + OFF_W1H);
    uint16_t* sW1l = (uint16_t*)(smc + OFF_W1L);
    uint16_t* sW2h = (uint16_t*)(smc + OFF_W2H);
    uint16_t* sW2l = (uint16_t*)(smc + OFF_W2L);
    float*    sb1  = (float*)(smc + OFF_B1);
    float*    sb2  = (float*)(smc + OFF_B2);

    const int tid = threadIdx.x;
    const int lane = tid & 31, w = tid >> 5;
    const int g = lane >> 2, qt = lane & 3;
    const int wm = w >> 1, wn = w & 1;

    {
        int n = tid & 127, k0 = (tid >> 7) * 64;
        for (int k = k0; k < k0 + 64; k += 2) {
            uint32_t hi, lo;
            split_pair(W1[k * 128 + n], W1[(k + 1) * 128 + n], hi, lo);
            *(uint32_t*)&sW1h[n * KP + k] = hi;
            *(uint32_t*)&sW1l[n * KP + k] = lo;
        }
    }
    {
        int n = tid & 63, k0 = (tid >> 6) * 32;
        for (int k = k0; k < k0 + 32; k += 2) {
            uint32_t hi, lo;
            split_pair(W2[k * 64 + n], W2[(k + 1) * 64 + n], hi, lo);
            *(uint32_t*)&sW2h[n * KP + k] = hi;
            *(uint32_t*)&sW2l[n * KP + k] = lo;
        }
    }
    if (tid < 128) sb1[tid] = b1[tid];
    if (tid < 64)  sb2[tid] = b2[tid];
    __syncthreads();

    for (int tile = blockIdx.x; tile < NT; tile += gridDim.x) {
        const int i0 = tile * 128;
        {
            const int m = tid & 127, half = tid >> 7;
            const int gi = i0 + m;
            const bool valid = gi < count;
            const float* src;
            float scale = 1.0f;
            bool doscale = false;
            if (half == 0) {
                src = x_src + (size_t)(valid ? gi : 0) * DD;
            } else {
                src = a_src + (size_t)(valid ? gi : 0) * DD;
                scale = valid ? (1.0f / fmaxf((float)cnt[gi], 1.0f)) : 0.0f;
                doscale = true;
            }
            #pragma unroll
            for (int c = 0; c < 64; c += 8) {
                float4 f0 = *(const float4*)(src + c);
                float4 f1 = *(const float4*)(src + c + 4);
                if (doscale) {
                    f0.x *= scale; f0.y *= scale; f0.z *= scale; f0.w *= scale;
                    f1.x *= scale; f1.y *= scale; f1.z *= scale; f1.w *= scale;
                }
                uint32_t hw[4], lw[4];
                split_pair(f0.x, f0.y, hw[0], lw[0]);
                split_pair(f0.z, f0.w, hw[1], lw[1]);
                split_pair(f1.x, f1.y, hw[2], lw[2]);
                split_pair(f1.z, f1.w, hw[3], lw[3]);
                int e = m * KP + half * 64 + c;
                *(uint4*)&sAh[e] = *(uint4*)hw;
                *(uint4*)&sAl[e] = *(uint4*)lw;
            }
        }
        __syncthreads();

        float acc[2][8][4];
        #pragma unroll
        for (int mt = 0; mt < 2; mt++)
            #pragma unroll
            for (int nt = 0; nt < 8; nt++)
                #pragma unroll
                for (int j = 0; j < 4; j++) acc[mt][nt][j] = 0.f;

        #pragma unroll
        for (int ks = 0; ks < 8; ks++) {
            const int kb = ks * 16 + 2 * qt;
            uint32_t ah[2][4], al[2][4];
            #pragma unroll
            for (int mt = 0; mt < 2; mt++) {
                int e = (wm * 32 + mt * 16 + g) * KP + kb;
                ah[mt][0] = *(const uint32_t*)&sAh[e];
                ah[mt][1] = *(const uint32_t*)&sAh[e + 8 * KP];
                ah[mt][2] = *(const uint32_t*)&sAh[e + 8];
                ah[mt][3] = *(const uint32_t*)&sAh[e + 8 * KP + 8];
                al[mt][0] = *(const uint32_t*)&sAl[e];
                al[mt][1] = *(const uint32_t*)&sAl[e + 8 * KP];
                al[mt][2] = *(const uint32_t*)&sAl[e + 8];
                al[mt][3] = *(const uint32_t*)&sAl[e + 8 * KP + 8];
            }
            #pragma unroll
            for (int nt = 0; nt < 8; nt++) {
                int e = (wn * 64 + nt * 8 + g) * KP + kb;
                uint32_t bh[2], bl[2];
                bh[0] = *(const uint32_t*)&sW1h[e];
                bh[1] = *(const uint32_t*)&sW1h[e + 8];
                bl[0] = *(const uint32_t*)&sW1l[e];
                bl[1] = *(const uint32_t*)&sW1l[e + 8];
                mma_bf16(acc[0][nt], ah[0], bh);
                mma_bf16(acc[1][nt], ah[1], bh);
                mma_bf16(acc[0][nt], ah[0], bl);
                mma_bf16(acc[1][nt], ah[1], bl);
                mma_bf16(acc[0][nt], al[0], bh);
                mma_bf16(acc[1][nt], al[1], bh);
            }
        }
        __syncthreads();

        #pragma unroll
        for (int mt = 0; mt < 2; mt++)
            #pragma unroll
            for (int nt = 0; nt < 8; nt++) {
                int row = wm * 32 + mt * 16 + g;
                int col = wn * 64 + nt * 8 + 2 * qt;
                float v0 = fmaxf(acc[mt][nt][0] + sb1[col], 0.f);
                float v1 = fmaxf(acc[mt][nt][1] + sb1[col + 1], 0.f);
                float v2 = fmaxf(acc[mt][nt][2] + sb1[col], 0.f);
                float v3 = fmaxf(acc[mt][nt][3] + sb1[col + 1], 0.f);
                uint32_t hi, lo;
                split_pair(v0, v1, hi, lo);
                *(uint32_t*)&sAh[row * KP + col] = hi;
                *(uint32_t*)&sAl[row * KP + col] = lo;
                split_pair(v2, v3, hi, lo);
                *(uint32_t*)&sAh[(row + 8) * KP + col] = hi;
                *(uint32_t*)&sAl[(row + 8) * KP + col] = lo;
            }
        __syncthreads();

        float acc2[2][4][4];
        #pragma unroll
        for (int mt = 0; mt < 2; mt++)
            #pragma unroll
            for (int nt = 0; nt < 4; nt++)
                #pragma unroll
                for (int j = 0; j < 4; j++) acc2[mt][nt][j] = 0.f;

        #pragma unroll
        for (int ks = 0; ks < 8; ks++) {
            const int kb = ks * 16 + 2 * qt;
            uint32_t ah[2][4], al[2][4];
            #pragma unroll
            for (int mt = 0; mt < 2; mt++) {
                int e = (wm * 32 + mt * 16 + g) * KP + kb;
                ah[mt][0] = *(const uint32_t*)&sAh[e];
                ah[mt][1] = *(const uint32_t*)&sAh[e + 8 * KP];
                ah[mt][2] = *(const uint32_t*)&sAh[e + 8];
                ah[mt][3] = *(const uint32_t*)&sAh[e + 8 * KP + 8];
                al[mt][0] = *(const uint32_t*)&sAl[e];
                al[mt][1] = *(const uint32_t*)&sAl[e + 8 * KP];
                al[mt][2] = *(const uint32_t*)&sAl[e + 8];
                al[mt][3] = *(const uint32_t*)&sAl[e + 8 * KP + 8];
            }
            #pragma unroll
            for (int nt = 0; nt < 4; nt++) {
                int e = (wn * 32 + nt * 8 + g) * KP + kb;
                uint32_t bh[2], bl[2];
                bh[0] = *(const uint32_t*)&sW2h[e];
                bh[1] = *(const uint32_t*)&sW2h[e + 8];
                bl[0] = *(const uint32_t*)&sW2l[e];
                bl[1] = *(const uint32_t*)&sW2l[e + 8];
                mma_bf16(acc2[0][nt], ah[0], bh);
                mma_bf16(acc2[1][nt], ah[1], bh);
                mma_bf16(acc2[0][nt], ah[0], bl);
                mma_bf16(acc2[1][nt], ah[1], bl);
                mma_bf16(acc2[0][nt], al[0], bh);
                mma_bf16(acc2[1][nt], al[1], bh);
            }
        }

        #pragma unroll
        for (int mt = 0; mt < 2; mt++)
            #pragma unroll
            for (int nt = 0; nt < 4; nt++) {
                int rl = wm * 32 + mt * 16 + g;
                int col = wn * 32 + nt * 8 + 2 * qt;
                #pragma unroll
                for (int rh = 0; rh < 2; rh++) {
                    int row = rl + rh * 8;
                    int gi = i0 + row;
                    if (gi >= count) continue;
                    float vx = acc2[mt][nt][rh * 2 + 0] + sb2[col];
                    float vy = acc2[mt][nt][rh * 2 + 1] + sb2[col + 1];
                    float2 rv = *(const float2*)(x_src + (size_t)gi * DD + col);
                    *(float2*)(dst + (size_t)gi * DD + col) =
                        make_float2(rv.x + vx, rv.y + vy);
                }
            }
        __syncthreads();
    }
}

extern "C" void kernel_launch(void* const* d_in, const int* in_sizes, int n_in,
                              void* d_out, int out_size)
{
    const float* x   = (const float*)d_in[0];
    const float* ea  = (const float*)d_in[1];
    const float* We1 = (const float*)d_in[2];
    const float* be1 = (const float*)d_in[3];
    const float* We2 = (const float*)d_in[4];
    const float* be2 = (const float*)d_in[5];
    const float* Wn1 = (const float*)d_in[6];
    const float* bn1 = (const float*)d_in[7];
    const float* Wn2 = (const float*)d_in[8];
    const float* bn2 = (const float*)d_in[9];
    const void*  eidx = d_in[10];

    float* out_x  = (float*)d_out;
    float* out_ea = (float*)d_out + (size_t)NN * DD;

    float *agg, *agg2, *Wc, *Px;
    int* cnt;
    cudaGetSymbolAddress((void**)&agg,  g_agg);
    cudaGetSymbolAddress((void**)&agg2, g_agg2);
    cudaGetSymbolAddress((void**)&cnt,  g_cnt);
    cudaGetSymbolAddress((void**)&Wc,   g_Wc);
    cudaGetSymbolAddress((void**)&Px,   g_Px);

    cudaFuncSetAttribute(edge_mma, cudaFuncAttributeMaxDynamicSharedMemorySize, E_SMEM);
    cudaFuncSetAttribute(node_mma, cudaFuncAttributeMaxDynamicSharedMemorySize, SMEMSZ);
    cudaFuncSetAttribute(px_k,     cudaFuncAttributeMaxDynamicSharedMemorySize, SMEMSZ);

    int smcount = 148;
    cudaDeviceGetAttribute(&smcount, cudaDevAttrMultiProcessorCount, 0);
    int ge = 2 * smcount < ET ? 2 * smcount : ET;
    int gn = smcount < NT ? smcount : NT;

    // Edge kernel stays at my launch index 3 (profiled by ncu -s 5 -c 1).
    prolog_k<<<(NN * DD / 4 + 255) / 256, 256>>>(eidx, agg, agg2, cnt);      // 0
    combine_count_k<<<(EE + 255) / 256, 256>>>(We1, Wc, eidx, cnt);          // 1
    px_k<<<gn, 256, SMEMSZ>>>(x, Wc, be1, Px);                               // 2
    edge_mma<<<ge, 256, E_SMEM>>>(ea, eidx, Px, Wc, We2, be2,                // 3 <- profiled
                                  out_ea, agg, ET);
    node_mma<<<gn, 256, SMEMSZ>>>(x, agg, Wn1, bn1, Wn2, bn2,                // 4
                                  out_x, cnt, NN);

    // iteration 2 (agg2 pre-zeroed in prolog -> no mid-stream zero pass)
    px_k<<<gn, 256, SMEMSZ>>>(out_x, Wc, be1, Px);                           // 5
    edge_mma<<<ge, 256, E_SMEM>>>(out_ea, eidx, Px, Wc, We2, be2,            // 6
                                  out_ea, agg2, ET);
    node_mma<<<gn, 256, SMEMSZ>>>(out_x, agg2, Wn1, bn1, Wn2, bn2,           // 7
                                  out_x, cnt, NN);
}

// round 17
// speedup vs baseline: 1.1910x; 1.0109x over previous
#include <cuda_runtime.h>
#include <cuda_bf16.h>
#include <cstdint>

#define NN 50000
#define EE 800000
#define DD 64
#define ET 6250                 // EE / 128
#define NT 391                  // ceil(NN / 128)
#define KP 136                  // px-kernel padded K stride (bf16)

// ---------------- device-global scratch (no allocations allowed) ----------
__device__ float g_agg[NN * DD];
__device__ float g_agg2[NN * DD];
__device__ int   g_cnt[NN];
__device__ float g_Wc[128 * 128];
__device__ float g_Px[NN * 128];   // per-node x @ Wc[0:64] + be1
__device__ int   g_is64;

__device__ __forceinline__ int load_row(const void* eidx, int i) {
    if (g_is64) return (int)((const long long*)eidx)[i];
    return ((const int*)eidx)[i];
}

// Prologue: zero BOTH agg buffers + cnt, detect eidx dtype.
__global__ void prolog_k(const void* eidx, float* agg1, float* agg2, int* cnt) {
    int i = blockIdx.x * blockDim.x + threadIdx.x;
    if (i < NN * DD / 4) {
        ((float4*)agg1)[i] = make_float4(0.f, 0.f, 0.f, 0.f);
        ((float4*)agg2)[i] = make_float4(0.f, 0.f, 0.f, 0.f);
    }
    if (i < NN) cnt[i] = 0;
    if (i == 0) {
        const long long* p = (const long long*)eidx;
        int ok = 1;
        for (int j = 0; j < 64; j++) {
            long long v = p[j];
            if (v < 0 || v >= NN) { ok = 0; break; }
        }
        g_is64 = ok;
    }
}

// Combine We1 halves + per-node edge count (cnt zeroed by prolog).
__global__ void combine_count_k(const float* __restrict__ We1, float* __restrict__ Wc,
                                const void* __restrict__ eidx, int* cnt) {
    int i = blockIdx.x * blockDim.x + threadIdx.x;
    if (i < 128 * 128) {
        int k = i >> 7, n = i & 127;
        float v = We1[(k + 64) * 128 + n];
        if (k < 64) v += We1[k * 128 + n];
        Wc[i] = v;
    }
    if (i < EE) atomicAdd(&cnt[load_row(eidx, i)], 1);
}

// ---------------- helpers ---------------------------------------------------
__device__ __forceinline__ void split_pair(float f0, float f1, uint32_t& hi, uint32_t& lo) {
    asm("cvt.rn.bf16x2.f32 %0, %1, %2;" : "=r"(hi) : "f"(f1), "f"(f0));
    float h0 = __uint_as_float(hi << 16);
    float h1 = __uint_as_float(hi & 0xFFFF0000u);
    float r0 = f0 - h0;
    float r1 = f1 - h1;
    asm("cvt.rn.bf16x2.f32 %0, %1, %2;" : "=r"(lo) : "f"(r1), "f"(r0));
}

__device__ __forceinline__ void mma_bf16(float* d, const uint32_t* a, const uint32_t* b) {
    asm volatile(
        "mma.sync.aligned.m16n8k16.row.col.f32.bf16.bf16.f32 "
        "{%0,%1,%2,%3}, {%4,%5,%6,%7}, {%8,%9}, {%0,%1,%2,%3};"
        : "+f"(d[0]), "+f"(d[1]), "+f"(d[2]), "+f"(d[3])
        : "r"(a[0]), "r"(a[1]), "r"(a[2]), "r"(a[3]), "r"(b[0]), "r"(b[1]));
}

// ================= EDGE KERNEL (round-16, unchanged: 290.9us) ==============
#define E_SA   0                  // 32KB: raw ea -> (later) D2 staging
#define E_SW1  32768              // W1: 4 planes x 128 rows x 64B
#define E_SW2  65536              // W2: 8 planes x 64 rows x 64B
#define E_B2   98304              // 64 f32
#define E_RW   98560              // 128 int rows
#define E_SMEM 99072

__global__ void __launch_bounds__(256, 2)
edge_mma(const float* __restrict__ ea, const void* __restrict__ eidx,
         const float* __restrict__ Px,
         const float* __restrict__ Wc, const float* __restrict__ W2,
         const float* __restrict__ b2,
         float* __restrict__ dst, float* __restrict__ agg, int ntiles)
{
    extern __shared__ char smc[];
    float* sb2  = (float*)(smc + E_B2);
    int*   sRows = (int*)(smc + E_RW);

    const int tid = threadIdx.x;
    const int lane = tid & 31, w = tid >> 5;
    const int g = lane >> 2, qt = lane & 3;
    const int mrow0 = 16 * w + g;

    {
        const int n = tid & 127, h = tid >> 7;
        uint32_t hi[16], lo[16];
        #pragma unroll
        for (int p = 0; p < 16; p++) {
            int k = 32 * h + 2 * p;
            split_pair(Wc[(64 + k) * 128 + n], Wc[(64 + k + 1) * 128 + n], hi[p], lo[p]);
        }
        #pragma unroll
        for (int ksl = 0; ksl < 2; ksl++)
            #pragma unroll
            for (int q = 0; q < 4; q++) {
                uint4 blk = make_uint4(hi[8 * ksl + q], hi[8 * ksl + q + 4],
                                       lo[8 * ksl + q], lo[8 * ksl + q + 4]);
                *(uint4*)(smc + E_SW1 + (2 * h + ksl) * 8192 + n * 64 + q * 16) = blk;
            }
    }
    {
        const int n = tid & 63, kq = tid >> 6;
        uint32_t hi[16], lo[16];
        #pragma unroll
        for (int p = 0; p < 16; p++) {
            int k = 32 * kq + 2 * p;
            split_pair(W2[k * 64 + n], W2[(k + 1) * 64 + n], hi[p], lo[p]);
        }
        #pragma unroll
        for (int ksl = 0; ksl < 2; ksl++)
            #pragma unroll
            for (int q = 0; q < 4; q++) {
                uint4 blk = make_uint4(hi[8 * ksl + q], hi[8 * ksl + q + 4],
                                       lo[8 * ksl + q], lo[8 * ksl + q + 4]);
                *(uint4*)(smc + E_SW2 + (2 * kq + ksl) * 4096 + n * 64 + q * 16) = blk;
            }
    }
    if (tid < 64) sb2[tid] = b2[tid];
    __syncthreads();

    const char* pB1 = smc + E_SW1 + g * 64 + qt * 16;
    const char* pB2 = smc + E_SW2 + g * 64 + qt * 16;
    const char* praw0 = smc + E_SA + mrow0 * 256;
    const char* praw1 = smc + E_SA + (mrow0 + 8) * 256;
    const int x0 = mrow0 & 15, x1 = (mrow0 + 8) & 15;
    const int coff = qt >> 1, soff = 8 * (qt & 1);

    for (int tile = blockIdx.x; tile < ntiles; tile += gridDim.x) {
        const int i0 = tile * 128;

        if (tid < 128) sRows[tid] = load_row(eidx, i0 + tid);
        const int r0 = load_row(eidx, i0 + mrow0);
        const int r1 = load_row(eidx, i0 + mrow0 + 8);

        {
            const uint4* src = (const uint4*)(ea + (size_t)i0 * DD);
            #pragma unroll
            for (int p = 0; p < 8; p++) {
                int id = p * 256 + tid;
                int row = id >> 4, c = id & 15;
                *(uint4*)(smc + E_SA + (row << 8) + (((c ^ (row & 15)) & 15) << 4)) = src[id];
            }
        }
        __syncthreads();

        uint32_t aH[4][4], aL[4][4];
        #pragma unroll
        for (int ks = 0; ks < 4; ks++) {
            int c = 4 * ks + coff;
            float2 f0 = *(const float2*)(praw0 + (((c     ^ x0) & 15) << 4) + soff);
            float2 f1 = *(const float2*)(praw1 + (((c     ^ x1) & 15) << 4) + soff);
            float2 f2 = *(const float2*)(praw0 + ((((c+2) ^ x0) & 15) << 4) + soff);
            float2 f3 = *(const float2*)(praw1 + ((((c+2) ^ x1) & 15) << 4) + soff);
            split_pair(f0.x, f0.y, aH[ks][0], aL[ks][0]);
            split_pair(f1.x, f1.y, aH[ks][1], aL[ks][1]);
            split_pair(f2.x, f2.y, aH[ks][2], aL[ks][2]);
            split_pair(f3.x, f3.y, aH[ks][3], aL[ks][3]);
        }

        float acc1[16][4];
        {
            const float* pr0 = Px + (size_t)r0 * 128 + 2 * qt;
            const float* pr1 = Px + (size_t)r1 * 128 + 2 * qt;
            #pragma unroll
            for (int nt = 0; nt < 16; nt++) {
                float2 v0 = *(const float2*)(pr0 + 8 * nt);
                float2 v1 = *(const float2*)(pr1 + 8 * nt);
                acc1[nt][0] = v0.x; acc1[nt][1] = v0.y;
                acc1[nt][2] = v1.x; acc1[nt][3] = v1.y;
            }
        }
        __syncthreads();

        #pragma unroll
        for (int ks = 0; ks < 4; ks++) {
            #pragma unroll
            for (int nt = 0; nt < 16; nt++) {
                uint4 B = *(const uint4*)(pB1 + ks * 8192 + nt * 512);
                uint32_t bh[2] = {B.x, B.y}, bl[2] = {B.z, B.w};
                mma_bf16(acc1[nt], aH[ks], bh);
                mma_bf16(acc1[nt], aH[ks], bl);
                mma_bf16(acc1[nt], aL[ks], bh);
            }
        }

        float acc2[8][4];
        #pragma unroll
        for (int nt = 0; nt < 8; nt++)
            #pragma unroll
            for (int j = 0; j < 4; j++) acc2[nt][j] = 0.f;

        #pragma unroll
        for (int ks = 0; ks < 8; ks++) {
            uint32_t hA[4], lA[4];
            float v00 = fmaxf(acc1[2 * ks][0], 0.f);
            float v01 = fmaxf(acc1[2 * ks][1], 0.f);
            float v02 = fmaxf(acc1[2 * ks][2], 0.f);
            float v03 = fmaxf(acc1[2 * ks][3], 0.f);
            float v10 = fmaxf(acc1[2 * ks + 1][0], 0.f);
            float v11 = fmaxf(acc1[2 * ks + 1][1], 0.f);
            float v12 = fmaxf(acc1[2 * ks + 1][2], 0.f);
            float v13 = fmaxf(acc1[2 * ks + 1][3], 0.f);
            split_pair(v00, v01, hA[0], lA[0]);
            split_pair(v02, v03, hA[1], lA[1]);
            split_pair(v10, v11, hA[2], lA[2]);
            split_pair(v12, v13, hA[3], lA[3]);
            #pragma unroll
            for (int nt = 0; nt < 8; nt++) {
                uint4 B = *(const uint4*)(pB2 + ks * 4096 + nt * 512);
                uint32_t bh[2] = {B.x, B.y}, bl[2] = {B.z, B.w};
                mma_bf16(acc2[nt], hA, bh);
                mma_bf16(acc2[nt], hA, bl);
                mma_bf16(acc2[nt], lA, bh);
            }
        }

        #pragma unroll
        for (int nt = 0; nt < 8; nt++) {
            int c = 2 * nt + (qt >> 1), s = qt & 1;
            {
                int r = mrow0;
                uint32_t a = (uint32_t)(r << 8) + ((uint32_t)((c ^ (r & 15)) & 15) << 4)
                           + ((uint32_t)s << 3);
                *(float2*)(smc + E_SA + a) = make_float2(acc2[nt][0], acc2[nt][1]);
            }
            {
                int r = mrow0 + 8;
                uint32_t a = (uint32_t)(r << 8) + ((uint32_t)((c ^ (r & 15)) & 15) << 4)
                           + ((uint32_t)s << 3);
                *(float2*)(smc + E_SA + a) = make_float2(acc2[nt][2], acc2[nt][3]);
            }
        }
        __syncthreads();

        {
            const float4* easrc = (const float4*)(ea + (size_t)i0 * DD);
            float4* dstp = (float4*)(dst + (size_t)i0 * DD);
            #pragma unroll
            for (int p = 0; p < 8; p++) {
                int id = p * 256 + tid;
                int row = id >> 4, c = id & 15;
                uint4 d = *(const uint4*)(smc + E_SA + (row << 8)
                                          + (((c ^ (row & 15)) & 15) << 4));
                float4 v;
                v.x = __uint_as_float(d.x) + sb2[4 * c + 0];
                v.y = __uint_as_float(d.y) + sb2[4 * c + 1];
                v.z = __uint_as_float(d.z) + sb2[4 * c + 2];
                v.w = __uint_as_float(d.w) + sb2[4 * c + 3];
                float* ap = agg + (size_t)sRows[row] * DD + 4 * c;
                asm volatile("red.global.add.v4.f32 [%0], {%1, %2, %3, %4};"
                             :: "l"(ap), "f"(v.x), "f"(v.y), "f"(v.z), "f"(v.w)
                             : "memory");
                float4 e = easrc[id];
                float4 o = make_float4(e.x + v.x, e.y + v.y, e.z + v.z, e.w + v.w);
                dstp[id] = o;
            }
        }
        __syncthreads();
    }
}

// ================= NODE KERNEL (edge-style port, occ 1) =====================
// A = [x | agg/max(cnt,1)], K=128. Planar W (zero-ALU loads), fragment-direct
// A converts from XOR-staged raw x/agg, bias-reg acc1 init, per-ks H pack,
// D2 staged into dead agg-raw buffer, x residual re-read from x-raw.
#define N_RAWX 0                   // 32KB: raw x (128 x 256B, XOR chunks)
#define N_RAWG 32768               // 32KB: raw agg -> D2 staging
#define N_W1   65536               // 64KB: 8 planes x 128 rows x 64B
#define N_W2   131072              // 32KB: 8 planes x 64 rows x 64B
#define N_B2   163840              // 64 f32
#define N_SMEM 164096

__global__ void __launch_bounds__(256, 1)
node_mma(const float* __restrict__ x_src, const float* __restrict__ agg,
         const int* __restrict__ cnt,
         const float* __restrict__ W1, const float* __restrict__ b1,
         const float* __restrict__ W2, const float* __restrict__ b2,
         float* __restrict__ dst, int count, int ntiles)
{
    extern __shared__ char smc[];
    float* sb2 = (float*)(smc + N_B2);

    const int tid = threadIdx.x;
    const int lane = tid & 31, w = tid >> 5;
    const int g = lane >> 2, qt = lane & 3;
    const int mrow0 = 16 * w + g;

    // ---- stage W1 (K=128) into planes 0..7 ----
    {
        const int n = tid & 127, h = tid >> 7;       // h covers k in [64h, 64h+64)
        uint32_t hi[32], lo[32];
        #pragma unroll
        for (int p = 0; p < 32; p++) {
            int k = 64 * h + 2 * p;
            split_pair(W1[k * 128 + n], W1[(k + 1) * 128 + n], hi[p], lo[p]);
        }
        #pragma unroll
        for (int ksl = 0; ksl < 4; ksl++)
            #pragma unroll
            for (int q = 0; q < 4; q++) {
                uint4 blk = make_uint4(hi[8 * ksl + q], hi[8 * ksl + q + 4],
                                       lo[8 * ksl + q], lo[8 * ksl + q + 4]);
                *(uint4*)(smc + N_W1 + (4 * h + ksl) * 8192 + n * 64 + q * 16) = blk;
            }
    }
    // ---- stage W2 (64n x K=128) into planes 0..7 ----
    {
        const int n = tid & 63, kq = tid >> 6;
        uint32_t hi[16], lo[16];
        #pragma unroll
        for (int p = 0; p < 16; p++) {
            int k = 32 * kq + 2 * p;
            split_pair(W2[k * 64 + n], W2[(k + 1) * 64 + n], hi[p], lo[p]);
        }
        #pragma unroll
        for (int ksl = 0; ksl < 2; ksl++)
            #pragma unroll
            for (int q = 0; q < 4; q++) {
                uint4 blk = make_uint4(hi[8 * ksl + q], hi[8 * ksl + q + 4],
                                       lo[8 * ksl + q], lo[8 * ksl + q + 4]);
                *(uint4*)(smc + N_W2 + (2 * kq + ksl) * 4096 + n * 64 + q * 16) = blk;
            }
    }
    if (tid < 64) sb2[tid] = b2[tid];

    // persistent bias regs for acc1 init (col = 8nt + 2qt + {0,1})
    float b1r[16][2];
    #pragma unroll
    for (int nt = 0; nt < 16; nt++) {
        float2 bv = *(const float2*)(b1 + 8 * nt + 2 * qt);
        b1r[nt][0] = bv.x; b1r[nt][1] = bv.y;
    }
    __syncthreads();

    const char* pB1 = smc + N_W1 + g * 64 + qt * 16;
    const char* pB2 = smc + N_W2 + g * 64 + qt * 16;
    const char* prx0 = smc + N_RAWX + mrow0 * 256;
    const char* prx1 = smc + N_RAWX + (mrow0 + 8) * 256;
    const char* prg0 = smc + N_RAWG + mrow0 * 256;
    const char* prg1 = smc + N_RAWG + (mrow0 + 8) * 256;
    const int x0 = mrow0 & 15, x1 = (mrow0 + 8) & 15;
    const int coff = qt >> 1, soff = 8 * (qt & 1);

    for (int tile = blockIdx.x; tile < ntiles; tile += gridDim.x) {
        const int i0 = tile * 128;

        // ---- raw staging: x and agg tiles (XOR chunk layout, guarded) ----
        {
            const uint4* srcx = (const uint4*)(x_src + (size_t)i0 * DD);
            const uint4* srcg = (const uint4*)(agg + (size_t)i0 * DD);
            #pragma unroll
            for (int p = 0; p < 8; p++) {
                int id = p * 256 + tid;
                int row = id >> 4, c = id & 15;
                uint4 v = make_uint4(0, 0, 0, 0), u = v;
                if (i0 + row < count) { v = srcx[id]; u = srcg[id]; }
                uint32_t a = (uint32_t)(row << 8) + (((uint32_t)(c ^ (row & 15)) & 15) << 4);
                *(uint4*)(smc + N_RAWX + a) = v;
                *(uint4*)(smc + N_RAWG + a) = u;
            }
        }
        const int r0g = i0 + mrow0, r1g = r0g + 8;
        const float s0 = (r0g < count) ? 1.0f / fmaxf((float)cnt[r0g], 1.0f) : 0.0f;
        const float s1 = (r1g < count) ? 1.0f / fmaxf((float)cnt[r1g], 1.0f) : 0.0f;
        __syncthreads();

        // ---- fragment-direct A converts: ks 0-3 from x, ks 4-7 from agg*s --
        uint32_t aH[8][4], aL[8][4];
        #pragma unroll
        for (int ks = 0; ks < 4; ks++) {
            int c = 4 * ks + coff;
            float2 f0 = *(const float2*)(prx0 + (((c     ^ x0) & 15) << 4) + soff);
            float2 f1 = *(const float2*)(prx1 + (((c     ^ x1) & 15) << 4) + soff);
            float2 f2 = *(const float2*)(prx0 + ((((c+2) ^ x0) & 15) << 4) + soff);
            float2 f3 = *(const float2*)(prx1 + ((((c+2) ^ x1) & 15) << 4) + soff);
            split_pair(f0.x, f0.y, aH[ks][0], aL[ks][0]);
            split_pair(f1.x, f1.y, aH[ks][1], aL[ks][1]);
            split_pair(f2.x, f2.y, aH[ks][2], aL[ks][2]);
            split_pair(f3.x, f3.y, aH[ks][3], aL[ks][3]);
        }
        #pragma unroll
        for (int ks = 0; ks < 4; ks++) {
            int c = 4 * ks + coff;
            float2 f0 = *(const float2*)(prg0 + (((c     ^ x0) & 15) << 4) + soff);
            float2 f1 = *(const float2*)(prg1 + (((c     ^ x1) & 15) << 4) + soff);
            float2 f2 = *(const float2*)(prg0 + ((((c+2) ^ x0) & 15) << 4) + soff);
            float2 f3 = *(const float2*)(prg1 + ((((c+2) ^ x1) & 15) << 4) + soff);
            split_pair(f0.x * s0, f0.y * s0, aH[4 + ks][0], aL[4 + ks][0]);
            split_pair(f1.x * s1, f1.y * s1, aH[4 + ks][1], aL[4 + ks][1]);
            split_pair(f2.x * s0, f2.y * s0, aH[4 + ks][2], aL[4 + ks][2]);
            split_pair(f3.x * s1, f3.y * s1, aH[4 + ks][3], aL[4 + ks][3]);
        }
        __syncthreads();   // raw reads done -> rawG reusable for D2 staging

        // ---- acc1 init from bias regs ----
        float acc1[16][4];
        #pragma unroll
        for (int nt = 0; nt < 16; nt++) {
            acc1[nt][0] = b1r[nt][0]; acc1[nt][1] = b1r[nt][1];
            acc1[nt][2] = b1r[nt][0]; acc1[nt][3] = b1r[nt][1];
        }

        // ---- GEMM1: acc1 += A @ W1 (K=128, 3 split terms) ----
        #pragma unroll
        for (int ks = 0; ks < 8; ks++) {
            #pragma unroll
            for (int nt = 0; nt < 16; nt++) {
                uint4 B = *(const uint4*)(pB1 + ks * 8192 + nt * 512);
                uint32_t bh[2] = {B.x, B.y}, bl[2] = {B.z, B.w};
                mma_bf16(acc1[nt], aH[ks], bh);
                mma_bf16(acc1[nt], aH[ks], bl);
                mma_bf16(acc1[nt], aL[ks], bh);
            }
        }

        // ---- GEMM2: per-ks pack (relu fused) then 8 MMAs ----
        float acc2[8][4];
        #pragma unroll
        for (int nt = 0; nt < 8; nt++)
            #pragma unroll
            for (int j = 0; j < 4; j++) acc2[nt][j] = 0.f;

        #pragma unroll
        for (int ks = 0; ks < 8; ks++) {
            uint32_t hA[4], lA[4];
            float v00 = fmaxf(acc1[2 * ks][0], 0.f);
            float v01 = fmaxf(acc1[2 * ks][1], 0.f);
            float v02 = fmaxf(acc1[2 * ks][2], 0.f);
            float v03 = fmaxf(acc1[2 * ks][3], 0.f);
            float v10 = fmaxf(acc1[2 * ks + 1][0], 0.f);
            float v11 = fmaxf(acc1[2 * ks + 1][1], 0.f);
            float v12 = fmaxf(acc1[2 * ks + 1][2], 0.f);
            float v13 = fmaxf(acc1[2 * ks + 1][3], 0.f);
            split_pair(v00, v01, hA[0], lA[0]);
            split_pair(v02, v03, hA[1], lA[1]);
            split_pair(v10, v11, hA[2], lA[2]);
            split_pair(v12, v13, hA[3], lA[3]);
            #pragma unroll
            for (int nt = 0; nt < 8; nt++) {
                uint4 B = *(const uint4*)(pB2 + ks * 4096 + nt * 512);
                uint32_t bh[2] = {B.x, B.y}, bl[2] = {B.z, B.w};
                mma_bf16(acc2[nt], hA, bh);
                mma_bf16(acc2[nt], hA, bl);
                mma_bf16(acc2[nt], lA, bh);
            }
        }

        // ---- stage D2 into rawG (XOR chunk layout) ----
        #pragma unroll
        for (int nt = 0; nt < 8; nt++) {
            int c = 2 * nt + (qt >> 1), s = qt & 1;
            {
                int r = mrow0;
                uint32_t a = (uint32_t)(r << 8) + ((uint32_t)((c ^ (r & 15)) & 15) << 4)
                           + ((uint32_t)s << 3);
                *(float2*)(smc + N_RAWG + a) = make_float2(acc2[nt][0], acc2[nt][1]);
            }
            {
                int r = mrow0 + 8;
                uint32_t a = (uint32_t)(r << 8) + ((uint32_t)((c ^ (r & 15)) & 15) << 4)
                           + ((uint32_t)s << 3);
                *(float2*)(smc + N_RAWG + a) = make_float2(acc2[nt][2], acc2[nt][3]);
            }
        }
        __syncthreads();

        // ---- coalesced epilogue: dst = x(rawX) + (D2 + b2), guarded ----
        {
            float4* dstp = (float4*)(dst + (size_t)i0 * DD);
            #pragma unroll
            for (int p = 0; p < 8; p++) {
                int id = p * 256 + tid;
                int row = id >> 4, c = id & 15;
                if (i0 + row >= count) continue;
                uint32_t a = (uint32_t)(row << 8) + (((uint32_t)(c ^ (row & 15)) & 15) << 4);
                uint4 d  = *(const uint4*)(smc + N_RAWG + a);
                uint4 xr = *(const uint4*)(smc + N_RAWX + a);
                float4 o;
                o.x = __uint_as_float(xr.x) + __uint_as_float(d.x) + sb2[4 * c + 0];
                o.y = __uint_as_float(xr.y) + __uint_as_float(d.y) + sb2[4 * c + 1];
                o.z = __uint_as_float(xr.z) + __uint_as_float(d.z) + sb2[4 * c + 2];
                o.w = __uint_as_float(xr.w) + __uint_as_float(d.w) + sb2[4 * c + 3];
                dstp[id] = o;
            }
        }
        __syncthreads();
    }
}

// ---------------- px kernel (round-16, known good) --------------------------
#define OFF_AH   0
#define OFF_AL   34816
#define OFF_W1H  69632
#define OFF_W1L  104448
#define OFF_B1   174080
#define SMEMSZ   175360

__global__ void __launch_bounds__(256, 1)
px_k(const float* __restrict__ x, const float* __restrict__ Wc,
     const float* __restrict__ be1, float* __restrict__ Px)
{
    extern __shared__ char smc[];
    uint16_t* sAh = (uint16_t*)(smc + OFF_AH);
    uint16_t* sAl = (uint16_t*)(smc + OFF_AL);
    uint16_t* sWh = (uint16_t*)(smc + OFF_W1H);
    uint16_t* sWl = (uint16_t*)(smc + OFF_W1L);
    float*    sb1 = (float*)(smc + OFF_B1);

    const int tid = threadIdx.x;
    const int lane = tid & 31, w = tid >> 5;
    const int g = lane >> 2, qt = lane & 3;
    const int wm = w >> 1, wn = w & 1;

    {
        int n = tid & 127, k0 = (tid >> 7) * 32;
        for (int k = k0; k < k0 + 32; k += 2) {
            uint32_t hi, lo;
            split_pair(Wc[k * 128 + n], Wc[(k + 1) * 128 + n], hi, lo);
            *(uint32_t*)&sWh[n * KP + k] = hi;
            *(uint32_t*)&sWl[n * KP + k] = lo;
        }
    }
    if (tid < 128) sb1[tid] = be1[tid];
    __syncthreads();

    for (int tile = blockIdx.x; tile < NT; tile += gridDim.x) {
        const int i0 = tile * 128;
        {
            const int m = tid & 127, ch = (tid >> 7) * 32;
            const int gi = i0 + m;
            const bool valid = gi < NN;
            const float* src = x + (size_t)(valid ? gi : 0) * DD + ch;
            #pragma unroll
            for (int c = 0; c < 32; c += 8) {
                float4 f0, f1;
                if (valid) { f0 = *(const float4*)(src + c); f1 = *(const float4*)(src + c + 4); }
                else { f0 = make_float4(0,0,0,0); f1 = f0; }
                uint32_t hw[4], lw[4];
                split_pair(f0.x, f0.y, hw[0], lw[0]);
                split_pair(f0.z, f0.w, hw[1], lw[1]);
                split_pair(f1.x, f1.y, hw[2], lw[2]);
                split_pair(f1.z, f1.w, hw[3], lw[3]);
                int e = m * KP + ch + c;
                *(uint4*)&sAh[e] = *(uint4*)hw;
                *(uint4*)&sAl[e] = *(uint4*)lw;
            }
        }
        __syncthreads();

        float acc[2][8][4];
        #pragma unroll
        for (int mt = 0; mt < 2; mt++)
            #pragma unroll
            for (int nt = 0; nt < 8; nt++)
                #pragma unroll
                for (int j = 0; j < 4; j++) acc[mt][nt][j] = 0.f;

        #pragma unroll
        for (int ks = 0; ks < 4; ks++) {
            const int kb = ks * 16 + 2 * qt;
            uint32_t ah[2][4], al[2][4];
            #pragma unroll
            for (int mt = 0; mt < 2; mt++) {
                int e = (wm * 32 + mt * 16 + g) * KP + kb;
                ah[mt][0] = *(const uint32_t*)&sAh[e];
                ah[mt][1] = *(const uint32_t*)&sAh[e + 8 * KP];
                ah[mt][2] = *(const uint32_t*)&sAh[e + 8];
                ah[mt][3] = *(const uint32_t*)&sAh[e + 8 * KP + 8];
                al[mt][0] = *(const uint32_t*)&sAl[e];
                al[mt][1] = *(const uint32_t*)&sAl[e + 8 * KP];
                al[mt][2] = *(const uint32_t*)&sAl[e + 8];
                al[mt][3] = *(const uint32_t*)&sAl[e + 8 * KP + 8];
            }
            #pragma unroll
            for (int nt = 0; nt < 8; nt++) {
                int e = (wn * 64 + nt * 8 + g) * KP + kb;
                uint32_t bh[2], bl[2];
                bh[0] = *(const uint32_t*)&sWh[e];
                bh[1] = *(const uint32_t*)&sWh[e + 8];
                bl[0] = *(const uint32_t*)&sWl[e];
                bl[1] = *(const uint32_t*)&sWl[e + 8];
                mma_bf16(acc[0][nt], ah[0], bh);
                mma_bf16(acc[1][nt], ah[1], bh);
                mma_bf16(acc[0][nt], ah[0], bl);
                mma_bf16(acc[1][nt], ah[1], bl);
                mma_bf16(acc[0][nt], al[0], bh);
                mma_bf16(acc[1][nt], al[1], bh);
            }
        }

        #pragma unroll
        for (int mt = 0; mt < 2; mt++)
            #pragma unroll
            for (int nt = 0; nt < 8; nt++) {
                int rl = wm * 32 + mt * 16 + g;
                int col = wn * 64 + nt * 8 + 2 * qt;
                #pragma unroll
                for (int rh = 0; rh < 2; rh++) {
                    int gi = i0 + rl + rh * 8;
                    if (gi >= NN) continue;
                    float2 v = make_float2(acc[mt][nt][rh * 2] + sb1[col],
                                           acc[mt][nt][rh * 2 + 1] + sb1[col + 1]);
                    *(float2*)&Px[(size_t)gi * 128 + col] = v;
                }
            }
        __syncthreads();
    }
}

extern "C" void kernel_launch(void* const* d_in, const int* in_sizes, int n_in,
                              void* d_out, int out_size)
{
    const float* x   = (const float*)d_in[0];
    const float* ea  = (const float*)d_in[1];
    const float* We1 = (const float*)d_in[2];
    const float* be1 = (const float*)d_in[3];
    const float* We2 = (const float*)d_in[4];
    const float* be2 = (const float*)d_in[5];
    const float* Wn1 = (const float*)d_in[6];
    const float* bn1 = (const float*)d_in[7];
    const float* Wn2 = (const float*)d_in[8];
    const float* bn2 = (const float*)d_in[9];
    const void*  eidx = d_in[10];

    float* out_x  = (float*)d_out;
    float* out_ea = (float*)d_out + (size_t)NN * DD;

    float *agg, *agg2, *Wc, *Px;
    int* cnt;
    cudaGetSymbolAddress((void**)&agg,  g_agg);
    cudaGetSymbolAddress((void**)&agg2, g_agg2);
    cudaGetSymbolAddress((void**)&cnt,  g_cnt);
    cudaGetSymbolAddress((void**)&Wc,   g_Wc);
    cudaGetSymbolAddress((void**)&Px,   g_Px);

    cudaFuncSetAttribute(edge_mma, cudaFuncAttributeMaxDynamicSharedMemorySize, E_SMEM);
    cudaFuncSetAttribute(node_mma, cudaFuncAttributeMaxDynamicSharedMemorySize, N_SMEM);
    cudaFuncSetAttribute(px_k,     cudaFuncAttributeMaxDynamicSharedMemorySize, SMEMSZ);

    int smcount = 148;
    cudaDeviceGetAttribute(&smcount, cudaDevAttrMultiProcessorCount, 0);
    int ge = 2 * smcount < ET ? 2 * smcount : ET;
    int gn = smcount < NT ? smcount : NT;

    // Edge kernel stays at my launch index 3 (profiled by ncu -s 5 -c 1).
    prolog_k<<<(NN * DD / 4 + 255) / 256, 256>>>(eidx, agg, agg2, cnt);      // 0
    combine_count_k<<<(EE + 255) / 256, 256>>>(We1, Wc, eidx, cnt);          // 1
    px_k<<<gn, 256, SMEMSZ>>>(x, Wc, be1, Px);                               // 2
    edge_mma<<<ge, 256, E_SMEM>>>(ea, eidx, Px, Wc, We2, be2,                // 3 <- profiled
                                  out_ea, agg, ET);
    node_mma<<<gn, 256, N_SMEM>>>(x, agg, cnt, Wn1, bn1, Wn2, bn2,           // 4
                                  out_x, NN, NT);

    // iteration 2 (agg2 pre-zeroed in prolog)
    px_k<<<gn, 256, SMEMSZ>>>(out_x, Wc, be1, Px);                           // 5
    edge_mma<<<ge, 256, E_SMEM>>>(out_ea, eidx, Px, Wc, We2, be2,            // 6
                                  out_ea, agg2, ET);
    node_mma<<<gn, 256, N_SMEM>>>(out_x, agg2, cnt, Wn1, bn1, Wn2, bn2,      // 7
                                  out_x, NN, NT);
}